// round 5
// baseline (speedup 1.0000x reference)
#include <cuda_runtime.h>

#define B_ 16
#define T_ 4096
#define C_ 512
#define K_ 3
#define L_ 128
#define G_ (T_ / L_)          // 32 chunks
#define CH_ 256               // channels per block
#define NH_ (C_ / CH_)        // 2 halves
#define NCHAIN_ (B_ * NH_)    // 32 independent carry chains
#define NBLK_ (G_ * NCHAIN_)  // 1024 blocks
#define EPSV 1e-4f

// Lookback scratch (no allocations allowed -> __device__ globals).
__device__ float g_E[NBLK_ * K_ * CH_];   // chunk-local end states (zero-init recurrence)
__device__ float g_V[NBLK_ * K_ * CH_];   // inclusive prefixes (exact carry-out)
__device__ int   g_flag[NBLK_];           // 0=none, 1=E ready, 2=V ready
__device__ int   g_ticket;

// ---------------------------------------------------------------------------
__global__ void reset_kernel() {
    int i = blockIdx.x * blockDim.x + threadIdx.x;
    if (i < NBLK_) g_flag[i] = 0;
    if (i == 0) g_ticket = 0;
}

// ---------------------------------------------------------------------------
__global__ void __launch_bounds__(CH_, 5)
ema_kernel(const float* __restrict__ x,
           const float* __restrict__ logit_alpha,
           const float* __restrict__ mix_logits,
           float* __restrict__ out) {
    __shared__ int sh_vid;
    __shared__ int sh_n;       // number of E-entries on the lookback path
    __shared__ int sh_term;    // pv holding a V terminator, or -1 => seed (x0)
    __shared__ int sh_path[G_];

    const int tid = threadIdx.x;

    // Ticket: virtual block id in scheduling order (deadlock-free lookback).
    if (tid == 0) sh_vid = atomicAdd(&g_ticket, 1);
    __syncthreads();
    const int vid   = sh_vid;
    const int j     = vid / NCHAIN_;   // chunk index along T
    const int chain = vid % NCHAIN_;   // (b, half)
    const int b     = chain / NH_;
    const int half  = chain % NH_;
    const int c     = half * CH_ + tid;

    // ---- per-channel coefficients ----
    float a0, a1, a2, b0, b1, b2, aL0, aL1, aL2;
    {
        float la0 = __ldg(logit_alpha + 0 * C_ + c);
        float la1 = __ldg(logit_alpha + 1 * C_ + c);
        float la2 = __ldg(logit_alpha + 2 * C_ + c);
        a0 = 1.0f / (1.0f + __expf(-la0));
        a1 = 1.0f / (1.0f + __expf(-la1));
        a2 = 1.0f / (1.0f + __expf(-la2));
        a0 = fminf(fmaxf(a0, EPSV), 1.0f - EPSV);
        a1 = fminf(fmaxf(a1, EPSV), 1.0f - EPSV);
        a2 = fminf(fmaxf(a2, EPSV), 1.0f - EPSV);
        b0 = 1.0f - a0; b1 = 1.0f - a1; b2 = 1.0f - a2;
        aL0 = a0; aL1 = a1; aL2 = a2;
        #pragma unroll
        for (int s = 0; s < 7; s++) { aL0 *= aL0; aL1 *= aL1; aL2 *= aL2; }  // a^128
    }
    float m0, m1, m2;
    {
        float l0 = __ldg(mix_logits + c * K_ + 0);
        float l1 = __ldg(mix_logits + c * K_ + 1);
        float l2 = __ldg(mix_logits + c * K_ + 2);
        float mx = fmaxf(l0, fmaxf(l1, l2));
        float e0 = __expf(l0 - mx), e1 = __expf(l1 - mx), e2 = __expf(l2 - mx);
        float inv = 1.0f / (e0 + e1 + e2);
        m0 = e0 * inv; m1 = e1 * inv; m2 = e2 * inv;
    }

    // Exact seed: y[-1] = x[b,0,c] makes y[0] = x[0].
    const float xb0 = __ldg(x + (size_t)b * T_ * C_ + c);

    // ---- phase 1: read x tile (HBM), compute zero-init end state E ----
    const float* xp = x + ((size_t)b * T_ + (size_t)j * L_) * C_ + c;
    float y0 = 0.0f, y1 = 0.0f, y2 = 0.0f;
    #pragma unroll
    for (int ii = 0; ii < L_; ii += 8) {
        float v[8];
        #pragma unroll
        for (int u = 0; u < 8; u++) v[u] = __ldg(xp + (size_t)(ii + u) * C_);
        #pragma unroll
        for (int u = 0; u < 8; u++) {
            y0 = fmaf(a0, y0, b0 * v[u]);
            y1 = fmaf(a1, y1, b1 * v[u]);
            y2 = fmaf(a2, y2, b2 * v[u]);
        }
    }

    // ---- publish E (flag=1) so successors can lookback immediately ----
    const int ebase = vid * (K_ * CH_) + tid;
    __stcg(&g_E[ebase + 0 * CH_], y0);
    __stcg(&g_E[ebase + 1 * CH_], y1);
    __stcg(&g_E[ebase + 2 * CH_], y2);
    __threadfence();
    __syncthreads();
    if (tid == 0) atomicExch(&g_flag[vid], 1);

    // ---- lookback path resolution: tid0 walks flags, records the path ----
    if (tid == 0) {
        int n = 0, term = -1;
        int pv = vid - NCHAIN_;
        while (pv >= 0) {
            int f;
            do {
                f = atomicAdd(&g_flag[pv], 0);
                if (f == 0) __nanosleep(50);
            } while (f == 0);
            if (f == 2) { term = pv; break; }
            sh_path[n++] = pv;           // flag==1: aggregate, keep walking
            pv -= NCHAIN_;
        }
        sh_n = n; sh_term = term;
    }
    __syncthreads();
    __threadfence();   // acquire: order path data loads after flag observations

    // ---- all threads: accumulate carry along the recorded path ----
    float c0, c1, c2;
    {
        const int n = sh_n, term = sh_term;
        float acc0 = 0.0f, acc1 = 0.0f, acc2 = 0.0f;
        float p0 = 1.0f, p1 = 1.0f, p2 = 1.0f;
        for (int d = 0; d < n; d++) {
            const float* src = g_E + sh_path[d] * (K_ * CH_) + tid;
            acc0 = fmaf(p0, __ldcg(src + 0 * CH_), acc0);
            acc1 = fmaf(p1, __ldcg(src + 1 * CH_), acc1);
            acc2 = fmaf(p2, __ldcg(src + 2 * CH_), acc2);
            p0 *= aL0; p1 *= aL1; p2 *= aL2;
        }
        float t0, t1, t2;
        if (term >= 0) {
            const float* src = g_V + term * (K_ * CH_) + tid;
            t0 = __ldcg(src + 0 * CH_);
            t1 = __ldcg(src + 1 * CH_);
            t2 = __ldcg(src + 2 * CH_);
        } else {
            t0 = xb0; t1 = xb0; t2 = xb0;   // seed (reached j = -1)
        }
        c0 = fmaf(p0, t0, acc0);
        c1 = fmaf(p1, t1, acc1);
        c2 = fmaf(p2, t2, acc2);
    }

    // ---- publish inclusive prefix V = aL*carry + E (flag=2) ----
    __stcg(&g_V[ebase + 0 * CH_], fmaf(aL0, c0, y0));
    __stcg(&g_V[ebase + 1 * CH_], fmaf(aL1, c1, y1));
    __stcg(&g_V[ebase + 2 * CH_], fmaf(aL2, c2, y2));
    __threadfence();
    __syncthreads();
    if (tid == 0) atomicExch(&g_flag[vid], 2);

    // ---- phase 2: rerun exact recurrence from carry; x re-read is L2-warm ----
    y0 = c0; y1 = c1; y2 = c2;
    float* op = out + ((size_t)b * T_ + (size_t)j * L_) * C_ + c;
    #pragma unroll
    for (int ii = 0; ii < L_; ii += 8) {
        float v[8];
        #pragma unroll
        for (int u = 0; u < 8; u++) v[u] = __ldg(xp + (size_t)(ii + u) * C_);
        #pragma unroll
        for (int u = 0; u < 8; u++) {
            y0 = fmaf(a0, y0, b0 * v[u]);
            y1 = fmaf(a1, y1, b1 * v[u]);
            y2 = fmaf(a2, y2, b2 * v[u]);
            op[(size_t)(ii + u) * C_] = fmaf(m2, y2, fmaf(m1, y1, m0 * y0));
        }
    }
}

// ---------------------------------------------------------------------------
extern "C" void kernel_launch(void* const* d_in, const int* in_sizes, int n_in,
                              void* d_out, int out_size) {
    const float* x           = (const float*)d_in[0];
    const float* logit_alpha = (const float*)d_in[1];
    const float* mix_logits  = (const float*)d_in[2];
    float*       out         = (float*)d_out;

    reset_kernel<<<(NBLK_ + 255) / 256, 256>>>();
    ema_kernel<<<NBLK_, CH_>>>(x, logit_alpha, mix_logits, out);
}

// round 6
// speedup vs baseline: 1.1813x; 1.1813x over previous
#include <cuda_runtime.h>
#include <cuda_fp16.h>

#define B_ 16
#define T_ 4096
#define C_ 512
#define K_ 3
#define L_ 64
#define G_ (T_ / L_)          // 64 chunks
#define CH_ 256               // channels per block
#define NH_ (C_ / CH_)        // 2 halves
#define NCHAIN_ (B_ * NH_)    // 32 independent carry chains
#define NBLK_ (G_ * NCHAIN_)  // 2048 blocks
#define EPSV 1e-4f

// Lookback scratch (no allocations allowed -> __device__ globals, zero-init).
__device__ float g_E[NBLK_ * K_ * CH_];   // chunk-local end states (zero-init recurrence)
__device__ float g_V[NBLK_ * K_ * CH_];   // inclusive prefixes (exact carry-out)
__device__ int   g_flag[NBLK_];           // epoch-tagged: 2*launch + {1:E, 2:V}
__device__ int   g_ticket;                // monotone across launches (epoch source)

// ---------------------------------------------------------------------------
__global__ void __launch_bounds__(CH_, 5)
ema_kernel(const float* __restrict__ x,
           const float* __restrict__ logit_alpha,
           const float* __restrict__ mix_logits,
           float* __restrict__ out) {
    __shared__ __half sx[L_ * CH_];   // mixed zero-init output stash (32 KB)
    __shared__ int sh_tvid;
    __shared__ int sh_n;              // E-entries on lookback path
    __shared__ int sh_term;           // vid holding V terminator, or -1 => seed
    __shared__ int sh_path[G_];

    const int tid = threadIdx.x;

    // Monotone ticket: encodes both launch epoch and scheduling-ordered vid.
    if (tid == 0) sh_tvid = atomicAdd(&g_ticket, 1);
    __syncthreads();
    const int tvid   = sh_tvid;
    const int launch = tvid / NBLK_;
    const int vid    = tvid % NBLK_;
    const int fbase  = 2 * launch;     // flag values below/equal fbase are stale
    const int j      = vid / NCHAIN_;  // chunk index along T
    const int chain  = vid % NCHAIN_;  // (b, half)
    const int b      = chain / NH_;
    const int half   = chain % NH_;
    const int c      = half * CH_ + tid;

    // ---- per-channel coefficients ----
    float a0, a1, a2, b0, b1, b2, aL0, aL1, aL2;
    {
        float la0 = __ldg(logit_alpha + 0 * C_ + c);
        float la1 = __ldg(logit_alpha + 1 * C_ + c);
        float la2 = __ldg(logit_alpha + 2 * C_ + c);
        a0 = 1.0f / (1.0f + __expf(-la0));
        a1 = 1.0f / (1.0f + __expf(-la1));
        a2 = 1.0f / (1.0f + __expf(-la2));
        a0 = fminf(fmaxf(a0, EPSV), 1.0f - EPSV);
        a1 = fminf(fmaxf(a1, EPSV), 1.0f - EPSV);
        a2 = fminf(fmaxf(a2, EPSV), 1.0f - EPSV);
        b0 = 1.0f - a0; b1 = 1.0f - a1; b2 = 1.0f - a2;
        aL0 = a0; aL1 = a1; aL2 = a2;
        #pragma unroll
        for (int s = 0; s < 6; s++) { aL0 *= aL0; aL1 *= aL1; aL2 *= aL2; }  // a^64
    }
    float m0, m1, m2;
    {
        float l0 = __ldg(mix_logits + c * K_ + 0);
        float l1 = __ldg(mix_logits + c * K_ + 1);
        float l2 = __ldg(mix_logits + c * K_ + 2);
        float mx = fmaxf(l0, fmaxf(l1, l2));
        float e0 = __expf(l0 - mx), e1 = __expf(l1 - mx), e2 = __expf(l2 - mx);
        float inv = 1.0f / (e0 + e1 + e2);
        m0 = e0 * inv; m1 = e1 * inv; m2 = e2 * inv;
    }

    // Exact seed: y[-1] = x[b,0,c] makes y[0] = x[0].
    const float xb0 = __ldg(x + (size_t)b * T_ * C_ + c);

    // ---- phase 1: single HBM read of x tile; zero-init recurrence;
    //      stash MIXED zero-output in fp16 smem; keep end states E ----
    const float* xp = x + ((size_t)b * T_ + (size_t)j * L_) * C_ + c;
    float y0 = 0.0f, y1 = 0.0f, y2 = 0.0f;
    #pragma unroll
    for (int ii = 0; ii < L_; ii += 8) {
        float v[8];
        #pragma unroll
        for (int u = 0; u < 8; u++) v[u] = __ldg(xp + (size_t)(ii + u) * C_);
        #pragma unroll
        for (int u = 0; u < 8; u++) {
            y0 = fmaf(a0, y0, b0 * v[u]);
            y1 = fmaf(a1, y1, b1 * v[u]);
            y2 = fmaf(a2, y2, b2 * v[u]);
            sx[(ii + u) * CH_ + tid] =
                __float2half(fmaf(m2, y2, fmaf(m1, y1, m0 * y0)));
        }
    }

    // ---- publish E (flag = fbase+1) ----
    const int ebase = vid * (K_ * CH_) + tid;
    __stcg(&g_E[ebase + 0 * CH_], y0);
    __stcg(&g_E[ebase + 1 * CH_], y1);
    __stcg(&g_E[ebase + 2 * CH_], y2);
    __threadfence();
    __syncthreads();
    if (tid == 0) atomicExch(&g_flag[vid], fbase + 1);

    // ---- lookback path resolution: tid0 walks flags, records the path ----
    if (tid == 0) {
        int n = 0, term = -1;
        int pv = vid - NCHAIN_;
        while (pv >= 0) {
            int f;
            do {
                f = atomicAdd(&g_flag[pv], 0) - fbase;   // stale => <= 0
                if (f <= 0) __nanosleep(50);
            } while (f <= 0);
            if (f == 2) { term = pv; break; }
            sh_path[n++] = pv;            // f==1: aggregate, keep walking
            pv -= NCHAIN_;
        }
        sh_n = n; sh_term = term;
    }
    __syncthreads();
    __threadfence();   // acquire: order E/V data loads after flag observations

    // ---- all threads: accumulate exact carry along the recorded path ----
    float c0, c1, c2;
    {
        const int n = sh_n, term = sh_term;
        float acc0 = 0.0f, acc1 = 0.0f, acc2 = 0.0f;
        float p0 = 1.0f, p1 = 1.0f, p2 = 1.0f;
        for (int d = 0; d < n; d++) {
            const float* src = g_E + sh_path[d] * (K_ * CH_) + tid;
            acc0 = fmaf(p0, __ldcg(src + 0 * CH_), acc0);
            acc1 = fmaf(p1, __ldcg(src + 1 * CH_), acc1);
            acc2 = fmaf(p2, __ldcg(src + 2 * CH_), acc2);
            p0 *= aL0; p1 *= aL1; p2 *= aL2;
        }
        float t0, t1, t2;
        if (term >= 0) {
            const float* src = g_V + term * (K_ * CH_) + tid;
            t0 = __ldcg(src + 0 * CH_);
            t1 = __ldcg(src + 1 * CH_);
            t2 = __ldcg(src + 2 * CH_);
        } else {
            t0 = xb0; t1 = xb0; t2 = xb0;   // reached j = -1: exact seed
        }
        c0 = fmaf(p0, t0, acc0);
        c1 = fmaf(p1, t1, acc1);
        c2 = fmaf(p2, t2, acc2);
    }

    // ---- publish inclusive prefix V = aL*carry + E (flag = fbase+2) ----
    __stcg(&g_V[ebase + 0 * CH_], fmaf(aL0, c0, y0));
    __stcg(&g_V[ebase + 1 * CH_], fmaf(aL1, c1, y1));
    __stcg(&g_V[ebase + 2 * CH_], fmaf(aL2, c2, y2));
    __threadfence();
    __syncthreads();
    if (tid == 0) atomicExch(&g_flag[vid], fbase + 2);

    // ---- phase 2: out[i] = s[i] + sum_k (m_k c_k) a_k^(i+1)  (exact identity;
    //      s[] carries the only approximation: one fp16 rounding) ----
    float pc0 = m0 * c0, pc1 = m1 * c1, pc2 = m2 * c2;
    float pw0 = a0, pw1 = a1, pw2 = a2;
    float* op = out + ((size_t)b * T_ + (size_t)j * L_) * C_ + c;
    #pragma unroll 8
    for (int i = 0; i < L_; i++) {
        float base = __half2float(sx[i * CH_ + tid]);
        float corr = fmaf(pc2, pw2, fmaf(pc1, pw1, pc0 * pw0));
        op[(size_t)i * C_] = base + corr;
        pw0 *= a0; pw1 *= a1; pw2 *= a2;
    }
}

// ---------------------------------------------------------------------------
extern "C" void kernel_launch(void* const* d_in, const int* in_sizes, int n_in,
                              void* d_out, int out_size) {
    const float* x           = (const float*)d_in[0];
    const float* logit_alpha = (const float*)d_in[1];
    const float* mix_logits  = (const float*)d_in[2];
    float*       out         = (float*)d_out;

    ema_kernel<<<NBLK_, CH_>>>(x, logit_alpha, mix_logits, out);
}